// round 17
// baseline (speedup 1.0000x reference)
#include <cuda_runtime.h>
#include <cuda_fp16.h>
#include <cstdint>

#define HH 300
#define G4 1200
#define NT 640              // 19 compute warps + producer warp 19
#define CLN 8
#define NCHUNK 4
#define CHUNK_MAX 48128     // steady chunk: 94 atoms x 512B

// SMEM layout (bytes)
#define SM_HX    0          // B matrix: 8 rows x 1216B (608 fp16: x 0-303, h 304-607)
#define SM_BAR   9728       // 4 x (full u64, empty u64)
#define SM_BIAS  9792       // biasf 4800 + bias2 4800
#define SM_CHUNK 19392
#define SM_TOTAL (SM_CHUNK + NCHUNK*CHUNK_MAX)   // 211904

// persistent globals (allocation-free rule)
__device__ __align__(256) float Wt2_g[600 * G4];   // [k][u*4+g] k<300:x, >=300:h
__device__ __align__(256) float Wc2_g[HH * G4];    // folded
__device__ __align__(256) float WoutT_g[HH * HH];  // [k][n]
__device__ __align__(256) float bias2_g[G4];
__device__ __align__(256) float biasf_g[G4];
__device__ __align__(256) __half A0_g[2850 * 256];   // step0: [j 0..37][t 0..74] atoms
__device__ __align__(256) __half ASTD_g[1786 * 256]; // steady: [j 0..18][t 0..93] atoms

__device__ __forceinline__ uint32_t smem_u32(const void* p) {
    uint32_t a;
    asm("{ .reg .u64 t; cvta.to.shared.u64 t, %1; cvt.u32.u64 %0, t; }" : "=r"(a) : "l"(p));
    return a;
}
__device__ __forceinline__ uint32_t ctarank() {
    uint32_t r; asm("mov.u32 %0, %%cluster_ctarank;" : "=r"(r)); return r;
}
__device__ __forceinline__ float sigf(float x) {
    return __fdividef(1.0f, 1.0f + __expf(-x));
}
__device__ __forceinline__ float tanhf_fast(float x) {
    return 1.0f - 2.0f * __fdividef(1.0f, __expf(2.0f * x) + 1.0f);
}
__device__ __forceinline__ void ldsm4(uint32_t* a, uint32_t addr) {
    asm volatile("ldmatrix.sync.aligned.m8n8.x4.shared.b16 {%0,%1,%2,%3},[%4];"
                 : "=r"(a[0]), "=r"(a[1]), "=r"(a[2]), "=r"(a[3]) : "r"(addr));
}
__device__ __forceinline__ void mma16(float* d, const uint32_t* a, uint32_t b0, uint32_t b1) {
    asm volatile(
        "mma.sync.aligned.m16n8k16.row.col.f32.f16.f16.f32 "
        "{%0,%1,%2,%3},{%4,%5,%6,%7},{%8,%9},{%0,%1,%2,%3};"
        : "+f"(d[0]), "+f"(d[1]), "+f"(d[2]), "+f"(d[3])
        : "r"(a[0]), "r"(a[1]), "r"(a[2]), "r"(a[3]), "r"(b0), "r"(b1));
}
__device__ __forceinline__ void mbar_init(uint32_t a, uint32_t c) {
    asm volatile("mbarrier.init.shared.b64 [%0], %1;" :: "r"(a), "r"(c) : "memory");
}
__device__ __forceinline__ void mbar_expect_tx(uint32_t a, uint32_t b) {
    asm volatile("mbarrier.arrive.expect_tx.shared.b64 _, [%0], %1;" :: "r"(a), "r"(b) : "memory");
}
__device__ __forceinline__ void mbar_arrive_cluster(uint32_t a, uint32_t rk) {
    asm volatile(
        "{\n\t.reg .b32 r;\n\t"
        "mapa.shared::cluster.u32 r, %0, %1;\n\t"
        "mbarrier.arrive.shared::cluster.b64 _, [r];\n\t}" :: "r"(a), "r"(rk) : "memory");
}
__device__ __forceinline__ void mbar_wait_acq(uint32_t a, uint32_t par) {
    asm volatile(
        "{ .reg .pred P;\nLW_%=:\n"
        "mbarrier.try_wait.parity.acquire.cta.shared::cta.b64 P, [%0], %1, 0x989680;\n"
        "@P bra.uni LD_%=;\nbra.uni LW_%=;\nLD_%=:\n}" :: "r"(a), "r"(par) : "memory");
}
__device__ __forceinline__ void mbar_wait_rlx(uint32_t a, uint32_t par) {
    asm volatile(
        "{ .reg .pred P;\nLW_%=:\n"
        "mbarrier.try_wait.parity.relaxed.cta.shared::cta.b64 P, [%0], %1, 0x989680;\n"
        "@P bra.uni LD_%=;\nbra.uni LW_%=;\nLD_%=:\n}" :: "r"(a), "r"(par) : "memory");
}
__device__ __forceinline__ void bulk_mc(uint32_t dst, const void* src, uint32_t bytes,
                                        uint32_t mbar, uint16_t m) {
    asm volatile(
        "cp.async.bulk.shared::cluster.global.mbarrier::complete_tx::bytes"
        ".multicast::cluster [%0], [%1], %2, [%3], %4;"
        :: "r"(dst), "l"(src), "r"(bytes), "r"(mbar), "h"(m) : "memory");
}

// ---------------- prep (proven R15) ----------------
__global__ void prep_basic(const float* W_ih, const float* W_hh, const float* b_ih,
                           const float* b_hh, const float* W_out) {
    int idx = blockIdx.x * blockDim.x + threadIdx.x;
    if (idx < 600 * G4) {
        int k = idx / G4, col = idx % G4, u = col >> 2, g = col & 3, n = u + HH * g;
        Wt2_g[idx] = (k < HH) ? W_ih[n * HH + k] : W_hh[n * HH + (k - HH)];
    }
    int i2 = idx - 600 * G4;
    if (i2 >= 0 && i2 < HH * HH) WoutT_g[i2] = W_out[(i2 % HH) * HH + (i2 / HH)];
    int i3 = idx - (600 * G4 + HH * HH);
    if (i3 >= 0 && i3 < G4) {
        int u = i3 >> 2, g = i3 & 3;
        bias2_g[i3] = b_ih[u + HH * g] + b_hh[u + HH * g];
    }
}
__global__ void prep_fold(const float* W_ih, const float* W_hh, const float* W_out) {
    __shared__ float sw[HH][20];
    int tid = threadIdx.x, kk = tid % 20, c = tid / 20;
    int k = blockIdx.y * 20 + kk, col = blockIdx.x * 16 + c;
    int u = col >> 2, g = col & 3, n = u + HH * g;
    for (int i = tid; i < HH * 20; i += 320)
        sw[i / 20][i % 20] = W_out[(i / 20) * HH + blockIdx.y * 20 + (i % 20)];
    __syncthreads();
    float acc = W_hh[n * HH + k];
    const float* wr = &W_ih[n * HH];
    #pragma unroll 4
    for (int j = 0; j < HH; ++j) acc = fmaf(__ldg(&wr[j]), sw[j][kk], acc);
    Wc2_g[k * G4 + col] = acc;
}
__global__ void prep_biasf(const float* W_ih, const float* b_ih, const float* b_hh,
                           const float* b_out) {
    int col = blockIdx.x * blockDim.x + threadIdx.x;
    if (col >= G4) return;
    int u = col >> 2, g = col & 3, n = u + HH * g;
    float acc = b_ih[n] + b_hh[n];
    const float* wr = &W_ih[n * HH];
    #pragma unroll 4
    for (int j = 0; j < HH; ++j) acc = fmaf(__ldg(&wr[j]), __ldg(&b_out[j]), acc);
    biasf_g[col] = acc;
}
// pack fp16 HMMA atoms (16x16 half, row stride 32B) — proven R15
__global__ void prep_pack() {
    int idx = blockIdx.x * blockDim.x + threadIdx.x;
    if (idx >= (2850 + 1786) * 256) return;
    int atom = idx >> 8, e = idx & 255, r = e >> 4, k16 = e & 15;
    float w = 0.f;
    if (atom < 2850) {                 // step0: j 0..37, t 0..74
        int j = atom / 75, t = atom - j * 75, col = 16 * t + r;
        if (j < 19) { int k = j * 16 + k16; if (k < 300) w = Wt2_g[k * G4 + col]; }
        else { int k = 300 + (j - 19) * 16 + k16; if (k < 600) w = Wt2_g[k * G4 + col]; }
        A0_g[idx] = __float2half(w);
    } else {                           // steady: j 0..18, t 0..93
        int a2 = atom - 2850;
        int j = a2 / 94, t = a2 - j * 94, k = j * 16 + k16;
        if (t < 75) { int col = 16 * t + r; if (k < 300) w = Wc2_g[k * G4 + col]; }
        else { int n = 16 * (t - 75) + r; if (k < 300 && n < 300) w = WoutT_g[k * HH + n]; }
        ASTD_g[a2 * 256 + e] = __float2half(w);
    }
}

// ---------------- persistent HMMA + cluster-8 multicast ring ----------------
__global__ void __launch_bounds__(NT, 1) __cluster_dims__(CLN, 1, 1)
lstm_tc(const float* __restrict__ h0, const float* __restrict__ c0,
        const float* __restrict__ start, const float* __restrict__ b_out,
        float* __restrict__ out, int B, int steps) {
    extern __shared__ char smem[];
    const uint32_t sb = smem_u32(smem);
    const uint32_t bar0 = sb + SM_BAR;
    const int tid = threadIdx.x, wid = tid >> 5, lane = tid & 31;
    const uint32_t rank = ctarank();
    const int r0 = blockIdx.x * 8;
    const int TOTAL = 38 + (steps - 1) * 19 + 19;

    if (tid == 0) {
        #pragma unroll
        for (int s = 0; s < NCHUNK; ++s) {
            mbar_init(bar0 + s * 16, 1);         // full: expect_tx based
            mbar_init(bar0 + s * 16 + 8, 152);   // empty: 19 warps x 8 CTAs
        }
    }
    // zero B region, copy biases
    for (int i = tid; i < 9728 / 4; i += NT) ((uint32_t*)(smem + SM_HX))[i] = 0;
    for (int i = tid; i < G4; i += NT) {
        ((float*)(smem + SM_BIAS))[i] = biasf_g[i];
        ((float*)(smem + SM_BIAS + 4800))[i] = bias2_g[i];
    }
    __syncthreads();
    // fill x0 (k 0-299) and h0 (k 304-603) as fp16
    for (int idx = tid; idx < HH * 8; idx += NT) {
        int u = idx >> 3, b = idx & 7;
        *(__half*)(smem + SM_HX + b * 1216 + u * 2) =
            __float2half(start[(size_t)(r0 + b) * HH + u]);
        *(__half*)(smem + SM_HX + b * 1216 + 608 + u * 2) =
            __float2half(h0[(size_t)(r0 + b) * HH + u]);
    }

    const int q = lane & 3, lr = lane >> 2;
    const bool owner = (lane & 15) < 4;
    const uint32_t lm_off = (uint32_t)((lane & 15) * 32 + (lane >> 4) * 16);
    const bool comp = (wid < 19);
    const bool isGateW = (wid < 15), isOutW = (wid >= 15 && wid < 19);

    // gate-warp owner state: c for 5 tiles x (2 units x 2 batch)
    float cst[5][4];
    int uAs[5];
    if (isGateW && owner) {
        #pragma unroll
        for (int i = 0; i < 5; ++i) {
            int T = wid * 5 + i;
            int uA = 4 * T + ((lane < 16) ? 0 : 1);
            uAs[i] = uA;
            #pragma unroll
            for (int c4 = 0; c4 < 4; ++c4) {
                int u = (c4 >> 1) ? (uA + 2) : uA;
                int ns = 2 * q + (c4 & 1);
                cst[i][c4] = c0[(size_t)(r0 + ns) * HH + u];
            }
        }
    }
    // out-warp biases
    float bo0[5], bo1[5];
    int n0s[5];
    if (isOutW) {
        #pragma unroll
        for (int i = 0; i < 5; ++i) {
            int T = wid * 5 + i;
            int n0 = 16 * (T - 75) + lr;
            n0s[i] = (T < 94) ? n0 : HH;
            bo0[i] = (T < 94 && n0 < HH) ? __ldg(&b_out[n0]) : 0.f;
            bo1[i] = (T < 94 && n0 + 8 < HH) ? __ldg(&b_out[n0 + 8]) : 0.f;
        }
    }
    __syncthreads();
    asm volatile("barrier.cluster.arrive.aligned;" ::: "memory");
    asm volatile("barrier.cluster.wait.aligned;" ::: "memory");

    // producer (thread 608): fetch 1/8 slice of every chunk, multicast to all 8
    int p_slot = 0, p_phase = 1;
    auto produce = [&](int g) {
        mbar_wait_rlx(bar0 + p_slot * 16 + 8, (uint32_t)p_phase);
        const char* src; int bytes;
        if (g < 38) {
            src = (const char*)A0_g + (size_t)g * 38400; bytes = 38400;
        } else if (g < 38 + (steps - 1) * 19) {
            int j = (g - 38) % 19;
            src = (const char*)ASTD_g + (size_t)j * 48128; bytes = 48128;
        } else {
            int j = g - 38 - (steps - 1) * 19;
            src = (const char*)ASTD_g + (size_t)j * 48128 + 75 * 512; bytes = 9728;
        }
        int slice = bytes >> 3;
        uint32_t full = bar0 + p_slot * 16;
        uint32_t dst = sb + SM_CHUNK + p_slot * CHUNK_MAX + rank * slice;
        mbar_expect_tx(full, (uint32_t)bytes);     // expect FULL chunk locally
        bulk_mc(dst, src + (size_t)rank * slice, (uint32_t)slice, full, 0xFF);
        if (++p_slot == NCHUNK) { p_slot = 0; p_phase ^= 1; }
    };
    if (tid == 608) {
        #pragma unroll
        for (int i = 0; i < NCHUNK; ++i) produce(i);
    }

    int c_slot = 0, c_phase = 0, gi = 0;
    float acc[5][4];

    // consume one chunk; mode 0=step0(gates only), 1=steady(all), 2=tail(out only)
    auto consume = [&](int ktB, int mode) {
        if (comp) {
            mbar_wait_acq(bar0 + c_slot * 16, (uint32_t)c_phase);
            uint32_t cb = sb + SM_CHUNK + c_slot * CHUNK_MAX;
            uint32_t boff = (uint32_t)(lr * 1216 + ktB * 32 + q * 4);
            uint32_t b0 = *(const uint32_t*)(smem + boff);
            uint32_t b1 = *(const uint32_t*)(smem + boff + 16);
            #pragma unroll
            for (int i = 0; i < 5; ++i) {
                int t = wid * 5 + i;
                bool go = (mode == 0) ? (t < 75)
                        : (mode == 2) ? (t >= 75 && t < 94) : (t < 94);
                if (go) {
                    uint32_t off = (uint32_t)((mode == 2 ? t - 75 : t) * 512);
                    uint32_t a[4];
                    ldsm4(a, cb + off + lm_off);
                    mma16(acc[i], a, b0, b1);
                }
            }
            if (lane == 0) {
                #pragma unroll
                for (int rk = 0; rk < CLN; ++rk)
                    mbar_arrive_cluster(bar0 + c_slot * 16 + 8, (uint32_t)rk);
            }
        }
        if (tid == 608 && gi + NCHUNK < TOTAL) produce(gi + NCHUNK);
        if (++c_slot == NCHUNK) { c_slot = 0; c_phase ^= 1; }
        ++gi;
    };
    auto reset_acc = [&]() {
        #pragma unroll
        for (int i = 0; i < 5; ++i)
            #pragma unroll
            for (int p = 0; p < 4; ++p) acc[i][p] = 0.f;
    };
    // gate epilogue: activations -> c,h; write h fp16 to SM_HX (h section)
    auto gate_epi = [&](bool step0) {
        #pragma unroll
        for (int i = 0; i < 5; ++i) {
            float fv[4], gv[4], ov[4];
            #pragma unroll
            for (int p = 0; p < 4; ++p) {
                fv[p] = __shfl_down_sync(0xffffffffu, acc[i][p], 4);
                gv[p] = __shfl_down_sync(0xffffffffu, acc[i][p], 8);
                ov[p] = __shfl_down_sync(0xffffffffu, acc[i][p], 12);
            }
            if (owner) {
                int uA = uAs[i];
                uint32_t bb = (uint32_t)SM_BIAS + (step0 ? 4800u : 0u);
                float4 bA = *(const float4*)(smem + bb + uA * 16);
                float4 bB = *(const float4*)(smem + bb + (uA + 2) * 16);
                #pragma unroll
                for (int c4 = 0; c4 < 4; ++c4) {
                    int ui = c4 >> 1, nn = c4 & 1;
                    int u = ui ? (uA + 2) : uA;
                    float4 bv = ui ? bB : bA;
                    float ii = sigf(acc[i][c4] + bv.x);
                    float ff = sigf(fv[c4] + bv.y);
                    float gg = tanhf_fast(gv[c4] + bv.z);
                    float oo = sigf(ov[c4] + bv.w);
                    float cc = fmaf(ff, cst[i][c4], ii * gg);
                    cst[i][c4] = cc;
                    float h = oo * tanhf_fast(cc);
                    int ns = 2 * q + nn;
                    *(__half*)(smem + ns * 1216 + 608 + u * 2) = __float2half(h);
                }
            }
        }
    };
    auto out_epi = [&](int tdst) {
        float* orow = out + ((size_t)tdst * B + r0) * HH;
        #pragma unroll
        for (int i = 0; i < 5; ++i) {
            int t = wid * 5 + i;
            if (t < 94) {
                int n0 = n0s[i], n1 = n0 + 8;
                if (n0 < HH) {
                    orow[(size_t)(2 * q) * HH + n0]     = acc[i][0] + bo0[i];
                    orow[(size_t)(2 * q + 1) * HH + n0] = acc[i][1] + bo0[i];
                }
                if (n1 < HH) {
                    orow[(size_t)(2 * q) * HH + n1]     = acc[i][2] + bo1[i];
                    orow[(size_t)(2 * q + 1) * HH + n1] = acc[i][3] + bo1[i];
                }
            }
        }
    };

    // ---- step 0: gates from (x0|h0), 38 k-slices ----
    reset_acc();
    for (int j = 0; j < 38; ++j) consume(j, 0);
    __syncthreads();
    if (isGateW) gate_epi(true);
    __syncthreads();

    // ---- steps 1..steps-1: out[s-1] + gates fused, 19 k-slices ----
    for (int s = 1; s < steps; ++s) {
        reset_acc();
        for (int j = 0; j < 19; ++j) consume(19 + j, 1);
        __syncthreads();
        if (isOutW) out_epi(s - 1);
        if (isGateW) gate_epi(false);
        __syncthreads();
    }

    // ---- tail: out[steps-1] from h_steps ----
    reset_acc();
    for (int j = 0; j < 19; ++j) consume(19 + j, 2);
    if (isOutW) out_epi(steps - 1);

    asm volatile("barrier.cluster.arrive.aligned;" ::: "memory");
    asm volatile("barrier.cluster.wait.aligned;" ::: "memory");
}

// ---------------- launch ----------------
extern "C" void kernel_launch(void* const* d_in, const int* in_sizes, int n_in,
                              void* d_out, int out_size) {
    const float* h0 = (const float*)d_in[0];
    const float* c0 = (const float*)d_in[1];
    const float* start = (const float*)d_in[2];
    const float* W_ih = (const float*)d_in[3];
    const float* W_hh = (const float*)d_in[4];
    const float* b_ih = (const float*)d_in[5];
    const float* b_hh = (const float*)d_in[6];
    const float* W_out = (const float*)d_in[7];
    const float* b_out = (const float*)d_in[8];
    int B = in_sizes[0] / HH;            // 1024
    int steps = out_size / (B * HH);     // 256

    int pe = 600 * G4 + HH * HH + G4;
    prep_basic<<<(pe + 255) / 256, 256>>>(W_ih, W_hh, b_ih, b_hh, W_out);
    dim3 fg(G4 / 16, HH / 20);
    prep_fold<<<fg, 320>>>(W_ih, W_hh, W_out);
    prep_biasf<<<(G4 + 255) / 256, 256>>>(W_ih, b_ih, b_hh, b_out);
    prep_pack<<<((2850 + 1786) * 256 + 255) / 256, 256>>>();

    cudaFuncSetAttribute(lstm_tc, cudaFuncAttributeMaxDynamicSharedMemorySize, SM_TOTAL);
    lstm_tc<<<B / 8, NT, SM_TOTAL>>>(h0, c0, start, b_out, (float*)d_out, B, steps);
}